// round 2
// baseline (speedup 1.0000x reference)
#include <cuda_runtime.h>
#include <cstdint>
#include <math.h>

// Problem constants
#define Tn   4096
#define Hn   1024
#define FH   4096          // 4*H
#define NCTA 128           // CTAs in recurrent kernel (<=148 SMs -> all co-resident, wave 1)
#define UPB  8             // hidden units per CTA (8 warps, 1 unit/warp)

#define CANARY_U 0xFFFFFFFFu   // NaN bit pattern; LSTM h can never be NaN

// ---------------------------------------------------------------------------
// Scratch (device globals -- no allocation allowed)
// ---------------------------------------------------------------------------
__device__ float d_G[(size_t)Tn * FH];       // 64 MB gate preactivations (reused by both layers)
__device__ float d_h0seq[(size_t)Tn * Hn];   // 16 MB layer-0 hidden sequence
__device__ float d_hring[2][4 * Hn];         // depth-4 canary ring per layer

// ---------------------------------------------------------------------------
// Memory-model helpers
// ---------------------------------------------------------------------------
__device__ __forceinline__ float4 ld_acq_v4(const float4* p) {
    float4 v;
    asm volatile("ld.acquire.gpu.global.v4.f32 {%0,%1,%2,%3}, [%4];"
                 : "=f"(v.x), "=f"(v.y), "=f"(v.z), "=f"(v.w)
                 : "l"(p) : "memory");
    return v;
}
__device__ __forceinline__ void st_rel_f32(float* p, float v) {
    asm volatile("st.release.gpu.global.f32 [%0], %1;" :: "l"(p), "f"(v) : "memory");
}
__device__ __forceinline__ void st_cg_f32(float* p, float v) {
    asm volatile("st.global.cg.f32 [%0], %1;" :: "l"(p), "f"(v) : "memory");
}
__device__ __forceinline__ bool is_canary(float v) {
    return __float_as_uint(v) == CANARY_U;
}

// fast activations (MUFU.EX2 based). Saturate correctly at +-inf.
__device__ __forceinline__ float sig_f(float x)  { return 1.f / (1.f + __expf(-x)); }
__device__ __forceinline__ float tanh_f(float x) { return 2.f / (1.f + __expf(-2.f * x)) - 1.f; }

// ---------------------------------------------------------------------------
// GEMM: C[M][N] = gather(A)[M][K] * B[N][K]^T + b1[N] + b2[N]   (NT GEMM)
// 128x128 tiles, KC=16, 8x8 microtile, k-major smem (+4 pad).
// ---------------------------------------------------------------------------
#define BM 128
#define BN 128
#define KC 16
#define BMP (BM + 4)
#define BNP (BN + 4)

__global__ __launch_bounds__(256, 1)
void gemm_nt_bias(const float* __restrict__ A, const int* __restrict__ aidx,
                  const float* __restrict__ B,
                  const float* __restrict__ b1, const float* __restrict__ b2,
                  float* __restrict__ C, int N, int K)
{
    __shared__ float sA[KC][BMP];
    __shared__ float sB[KC][BNP];

    const int nbx = N / BN;
    const int bx  = blockIdx.x % nbx;
    const int by  = blockIdx.x / nbx;
    const int tid = threadIdx.x;
    const int tx  = tid & 15;
    const int ty  = tid >> 4;
    const int row0 = by * BM, col0 = bx * BN;

    const int lr = tid >> 2;          // 0..63
    const int ks = (tid & 3) << 2;    // 0,4,8,12

    size_t aoff0, aoff1;
    {
        int r0 = row0 + lr, r1 = r0 + 64;
        int g0 = aidx ? aidx[r0] : r0;
        int g1 = aidx ? aidx[r1] : r1;
        aoff0 = (size_t)g0 * K + ks;
        aoff1 = (size_t)g1 * K + ks;
    }
    size_t boff0 = (size_t)(col0 + lr) * K + ks;
    size_t boff1 = boff0 + (size_t)64 * K;

    float acc[8][8];
    #pragma unroll
    for (int i = 0; i < 8; i++)
        #pragma unroll
        for (int j = 0; j < 8; j++) acc[i][j] = 0.f;

    #pragma unroll 1
    for (int k0 = 0; k0 < K; k0 += KC) {
        float4 va0 = *(const float4*)(A + aoff0 + k0);
        float4 va1 = *(const float4*)(A + aoff1 + k0);
        float4 vb0 = *(const float4*)(B + boff0 + k0);
        float4 vb1 = *(const float4*)(B + boff1 + k0);
        __syncthreads();
        sA[ks+0][lr]    = va0.x; sA[ks+1][lr]    = va0.y; sA[ks+2][lr]    = va0.z; sA[ks+3][lr]    = va0.w;
        sA[ks+0][lr+64] = va1.x; sA[ks+1][lr+64] = va1.y; sA[ks+2][lr+64] = va1.z; sA[ks+3][lr+64] = va1.w;
        sB[ks+0][lr]    = vb0.x; sB[ks+1][lr]    = vb0.y; sB[ks+2][lr]    = vb0.z; sB[ks+3][lr]    = vb0.w;
        sB[ks+0][lr+64] = vb1.x; sB[ks+1][lr+64] = vb1.y; sB[ks+2][lr+64] = vb1.z; sB[ks+3][lr+64] = vb1.w;
        __syncthreads();
        #pragma unroll
        for (int kk = 0; kk < KC; kk++) {
            float4 a0v = *(const float4*)&sA[kk][ty * 8];
            float4 a1v = *(const float4*)&sA[kk][ty * 8 + 4];
            float4 b0v = *(const float4*)&sB[kk][tx * 8];
            float4 b1v = *(const float4*)&sB[kk][tx * 8 + 4];
            float ar[8] = {a0v.x, a0v.y, a0v.z, a0v.w, a1v.x, a1v.y, a1v.z, a1v.w};
            float br[8] = {b0v.x, b0v.y, b0v.z, b0v.w, b1v.x, b1v.y, b1v.z, b1v.w};
            #pragma unroll
            for (int i = 0; i < 8; i++)
                #pragma unroll
                for (int j = 0; j < 8; j++)
                    acc[i][j] += ar[i] * br[j];
        }
    }

    float bsum[8];
    #pragma unroll
    for (int j = 0; j < 8; j++) {
        int col = col0 + tx * 8 + j;
        bsum[j] = b1[col] + b2[col];
    }
    #pragma unroll
    for (int i = 0; i < 8; i++) {
        int row = row0 + ty * 8 + i;
        float4 o0 = make_float4(acc[i][0] + bsum[0], acc[i][1] + bsum[1],
                                acc[i][2] + bsum[2], acc[i][3] + bsum[3]);
        float4 o1 = make_float4(acc[i][4] + bsum[4], acc[i][5] + bsum[5],
                                acc[i][6] + bsum[6], acc[i][7] + bsum[7]);
        float* crow = C + (size_t)row * N + col0 + tx * 8;
        *(float4*)(crow)     = o0;
        *(float4*)(crow + 4) = o1;
    }
}

// ---------------------------------------------------------------------------
// Recurrent LSTM layer with canary-ring dataflow sync (NO counter barrier).
//
// ring = 4 slots x 1024 floats, initialized to CANARY (NaN). Step t:
//   - consumers acquire-poll slot (t-1)&3 directly into smem (poll == load)
//   - __syncthreads()  -> this CTA observed ALL 1024 writes of step t-1,
//     hence every CTA consumed step t-2
//   - lane0 resets slot (t+2)&3 (holds step t-2 data) to CANARY
//   - compute; lane0 release-stores h into slot t&3 (reset at step t-2)
// Smem h stage is double-buffered -> single __syncthreads per step.
// ---------------------------------------------------------------------------
__global__ __launch_bounds__(256, 1)
void lstm_layer_kernel(const float* __restrict__ Whh,   // [4H][H]
                       const float* __restrict__ G,     // [T][4H]
                       float* __restrict__ seq,         // [T][H]
                       float* __restrict__ hT, float* __restrict__ cT,
                       float* __restrict__ ring)        // [4][H], canary-filled
{
    const int tid  = threadIdx.x;
    const int warp = tid >> 5;
    const int lane = tid & 31;
    const int unit = blockIdx.x * UPB + warp;

    // Register-resident weights: lane covers elements i*128 + lane*4 + c
    float4 w[4][8];
    #pragma unroll
    for (int g = 0; g < 4; g++) {
        const float4* wr = (const float4*)(Whh + (size_t)(g * Hn + unit) * Hn);
        #pragma unroll
        for (int i = 0; i < 8; i++)
            w[g][i] = wr[i * 32 + lane];
    }

    __shared__ float4 sh[2][Hn / 4];   // double-buffered staged h_{t-1}

    const float canf = __uint_as_float(CANARY_U);
    float c = 0.f;

    #pragma unroll 1
    for (int t = 0; t < Tn; t++) {
        // prefetch gate preactivations (independent of h)
        const float* gp = G + (size_t)t * FH + unit;
        float gv0 = __ldg(gp);
        float gv1 = __ldg(gp + Hn);
        float gv2 = __ldg(gp + 2 * Hn);
        float gv3 = __ldg(gp + 3 * Hn);

        float a0 = 0.f, a1 = 0.f, a2 = 0.f, a3 = 0.f;
        if (t > 0) {
            // acquire-poll h_{t-1}: the poll IS the data load
            const float4* src = (const float4*)(ring + ((t - 1) & 3) * Hn) + tid;
            float4 hv;
            do {
                hv = ld_acq_v4(src);
            } while (is_canary(hv.x) | is_canary(hv.y) | is_canary(hv.z) | is_canary(hv.w));
            sh[t & 1][tid] = hv;
            __syncthreads();
            // recycle ring slot of step t-2 (provably consumed by all CTAs)
            if (lane == 0)
                st_cg_f32(ring + ((t + 2) & 3) * Hn + unit, canf);

            const float4* shp = sh[t & 1];
            #pragma unroll
            for (int i = 0; i < 8; i++) {
                float4 h4 = shp[i * 32 + lane];
                a0 += w[0][i].x * h4.x; a0 += w[0][i].y * h4.y; a0 += w[0][i].z * h4.z; a0 += w[0][i].w * h4.w;
                a1 += w[1][i].x * h4.x; a1 += w[1][i].y * h4.y; a1 += w[1][i].z * h4.z; a1 += w[1][i].w * h4.w;
                a2 += w[2][i].x * h4.x; a2 += w[2][i].y * h4.y; a2 += w[2][i].z * h4.z; a2 += w[2][i].w * h4.w;
                a3 += w[3][i].x * h4.x; a3 += w[3][i].y * h4.y; a3 += w[3][i].z * h4.z; a3 += w[3][i].w * h4.w;
            }
        } else {
            if (lane == 0)   // clears an initial-canary slot; harmless
                st_cg_f32(ring + ((t + 2) & 3) * Hn + unit, canf);
        }

        // full-warp butterfly reduce
        #pragma unroll
        for (int off = 16; off; off >>= 1) {
            a0 += __shfl_xor_sync(0xFFFFFFFFu, a0, off);
            a1 += __shfl_xor_sync(0xFFFFFFFFu, a1, off);
            a2 += __shfl_xor_sync(0xFFFFFFFFu, a2, off);
            a3 += __shfl_xor_sync(0xFFFFFFFFu, a3, off);
        }

        float ig = sig_f(gv0 + a0);
        float fg = sig_f(gv1 + a1);
        float gg = tanh_f(gv2 + a2);
        float og = sig_f(gv3 + a3);
        c = fg * c + ig * gg;
        float h = og * tanh_f(c);

        if (lane == 0) {
            st_rel_f32(ring + (t & 3) * Hn + unit, h);   // release: publishes h + reset
            seq[(size_t)t * Hn + unit] = h;
            if (t == Tn - 1) { hT[unit] = h; cT[unit] = c; }
        }
    }
}

// ---------------------------------------------------------------------------
// Launch: memset canary rings -> GEMM0 -> layer0 -> GEMM1 -> layer1
// ---------------------------------------------------------------------------
extern "C" void kernel_launch(void* const* d_in, const int* in_sizes, int n_in,
                              void* d_out, int out_size)
{
    const int*   tok = (const int*)d_in[0];
    const float* emb = (const float*)d_in[1];
    const float* Wih = (const float*)d_in[2];
    const float* Whh = (const float*)d_in[3];
    const float* bih = (const float*)d_in[4];
    const float* bhh = (const float*)d_in[5];
    float* out = (float*)d_out;

    float *G, *h0seq, *ring;
    cudaGetSymbolAddress((void**)&G,     d_G);
    cudaGetSymbolAddress((void**)&h0seq, d_h0seq);
    cudaGetSymbolAddress((void**)&ring,  d_hring);

    // fill both rings with the canary NaN pattern (re-done every graph replay)
    cudaMemsetAsync(ring, 0xFF, sizeof(float) * 2 * 4 * Hn, 0);

    float* outs = out;                        // [T][H]
    float* hTp  = out + (size_t)Tn * Hn;      // [L][H]
    float* cTp  = hTp + 2 * Hn;               // [L][H]

    const int gemm_grid = (Tn / BM) * (FH / BN);   // 1024

    // Layer 0 input projection: G = emb[tok] @ W_ih0^T + b_ih0 + b_hh0
    gemm_nt_bias<<<gemm_grid, 256>>>(emb, tok, Wih, bih, bhh, G, FH, Hn);

    // Layer 0 recurrence
    lstm_layer_kernel<<<NCTA, 256>>>(Whh, G, h0seq, hTp, cTp, ring);

    // Layer 1 input projection: G = h0seq @ W_ih1^T + b_ih1 + b_hh1
    gemm_nt_bias<<<gemm_grid, 256>>>(h0seq, nullptr, Wih + (size_t)FH * Hn,
                                     bih + FH, bhh + FH, G, FH, Hn);

    // Layer 1 recurrence (writes outs + final states)
    lstm_layer_kernel<<<NCTA, 256>>>(Whh + (size_t)FH * Hn, G, outs,
                                     hTp + Hn, cTp + Hn, ring + 4 * Hn);
}

// round 5
// speedup vs baseline: 1.4049x; 1.4049x over previous
#include <cuda_runtime.h>
#include <cstdint>
#include <math.h>

// Problem constants
#define Tn   4096
#define Hn   1024
#define FH   4096          // 4*H
#define NCTA 128           // recurrent CTAs (<=148 SMs -> all co-resident in wave 1)
#define UPB  8             // hidden units per CTA (8 warps, 1 unit/warp)
#define FPAD 32            // flag padding: 32 uints = one 128B line per flag

// ---------------------------------------------------------------------------
// Scratch (device globals -- no allocation allowed)
// ---------------------------------------------------------------------------
__device__ float    d_G[(size_t)Tn * FH];       // 64 MB gate preactivations (reused by both layers)
__device__ float    d_h0seq[(size_t)Tn * Hn];   // 16 MB layer-0 hidden sequence
__device__ float    d_hbuf[2][2 * Hn];          // per-layer double-buffered h
__device__ unsigned d_flag[2][NCTA * FPAD];     // per-layer distributed step flags (1 line/CTA)

// ---------------------------------------------------------------------------
// Memory-model helpers
// ---------------------------------------------------------------------------
__device__ __forceinline__ unsigned ld_acq_u32(const unsigned* p) {
    unsigned v;
    asm volatile("ld.acquire.gpu.global.u32 %0, [%1];" : "=r"(v) : "l"(p) : "memory");
    return v;
}
__device__ __forceinline__ void st_rel_u32(unsigned* p, unsigned v) {
    asm volatile("st.release.gpu.global.u32 [%0], %1;" :: "l"(p), "r"(v) : "memory");
}
__device__ __forceinline__ float4 ld_cg_v4(const float4* p) {
    float4 v;
    asm volatile("ld.global.cg.v4.f32 {%0,%1,%2,%3}, [%4];"
                 : "=f"(v.x), "=f"(v.y), "=f"(v.z), "=f"(v.w) : "l"(p) : "memory");
    return v;
}
__device__ __forceinline__ void st_cg_v4(float4* p, float4 v) {
    asm volatile("st.global.cg.v4.f32 [%0], {%1,%2,%3,%4};"
                 :: "l"(p), "f"(v.x), "f"(v.y), "f"(v.z), "f"(v.w) : "memory");
}

// fast activations (MUFU.EX2 based); saturate correctly at +-inf
__device__ __forceinline__ float sig_f(float x)  { return 1.f / (1.f + __expf(-x)); }
__device__ __forceinline__ float tanh_f(float x) { return 2.f / (1.f + __expf(-2.f * x)) - 1.f; }

// ---------------------------------------------------------------------------
// GEMM: C[M][N] = gather(A)[M][K] * B[N][K]^T + b1[N] + b2[N]   (NT GEMM)
// 128x128 tiles, KC=16, 8x8 microtile, k-major smem (+4 pad).
// ---------------------------------------------------------------------------
#define BM 128
#define BN 128
#define KC 16
#define BMP (BM + 4)
#define BNP (BN + 4)

__global__ __launch_bounds__(256, 1)
void gemm_nt_bias(const float* __restrict__ A, const int* __restrict__ aidx,
                  const float* __restrict__ B,
                  const float* __restrict__ b1, const float* __restrict__ b2,
                  float* __restrict__ C, int N, int K)
{
    __shared__ float sA[KC][BMP];
    __shared__ float sB[KC][BNP];

    const int nbx = N / BN;
    const int bx  = blockIdx.x % nbx;
    const int by  = blockIdx.x / nbx;
    const int tid = threadIdx.x;
    const int tx  = tid & 15;
    const int ty  = tid >> 4;
    const int row0 = by * BM, col0 = bx * BN;

    const int lr = tid >> 2;          // 0..63
    const int ks = (tid & 3) << 2;    // 0,4,8,12

    size_t aoff0, aoff1;
    {
        int r0 = row0 + lr, r1 = r0 + 64;
        int g0 = aidx ? aidx[r0] : r0;
        int g1 = aidx ? aidx[r1] : r1;
        aoff0 = (size_t)g0 * K + ks;
        aoff1 = (size_t)g1 * K + ks;
    }
    size_t boff0 = (size_t)(col0 + lr) * K + ks;
    size_t boff1 = boff0 + (size_t)64 * K;

    float acc[8][8];
    #pragma unroll
    for (int i = 0; i < 8; i++)
        #pragma unroll
        for (int j = 0; j < 8; j++) acc[i][j] = 0.f;

    #pragma unroll 1
    for (int k0 = 0; k0 < K; k0 += KC) {
        float4 va0 = *(const float4*)(A + aoff0 + k0);
        float4 va1 = *(const float4*)(A + aoff1 + k0);
        float4 vb0 = *(const float4*)(B + boff0 + k0);
        float4 vb1 = *(const float4*)(B + boff1 + k0);
        __syncthreads();
        sA[ks+0][lr]    = va0.x; sA[ks+1][lr]    = va0.y; sA[ks+2][lr]    = va0.z; sA[ks+3][lr]    = va0.w;
        sA[ks+0][lr+64] = va1.x; sA[ks+1][lr+64] = va1.y; sA[ks+2][lr+64] = va1.z; sA[ks+3][lr+64] = va1.w;
        sB[ks+0][lr]    = vb0.x; sB[ks+1][lr]    = vb0.y; sB[ks+2][lr]    = vb0.z; sB[ks+3][lr]    = vb0.w;
        sB[ks+0][lr+64] = vb1.x; sB[ks+1][lr+64] = vb1.y; sB[ks+2][lr+64] = vb1.z; sB[ks+3][lr+64] = vb1.w;
        __syncthreads();
        #pragma unroll
        for (int kk = 0; kk < KC; kk++) {
            float4 a0v = *(const float4*)&sA[kk][ty * 8];
            float4 a1v = *(const float4*)&sA[kk][ty * 8 + 4];
            float4 b0v = *(const float4*)&sB[kk][tx * 8];
            float4 b1v = *(const float4*)&sB[kk][tx * 8 + 4];
            float ar[8] = {a0v.x, a0v.y, a0v.z, a0v.w, a1v.x, a1v.y, a1v.z, a1v.w};
            float br[8] = {b0v.x, b0v.y, b0v.z, b0v.w, b1v.x, b1v.y, b1v.z, b1v.w};
            #pragma unroll
            for (int i = 0; i < 8; i++)
                #pragma unroll
                for (int j = 0; j < 8; j++)
                    acc[i][j] += ar[i] * br[j];
        }
    }

    float bsum[8];
    #pragma unroll
    for (int j = 0; j < 8; j++) {
        int col = col0 + tx * 8 + j;
        bsum[j] = b1[col] + b2[col];
    }
    #pragma unroll
    for (int i = 0; i < 8; i++) {
        int row = row0 + ty * 8 + i;
        float4 o0 = make_float4(acc[i][0] + bsum[0], acc[i][1] + bsum[1],
                                acc[i][2] + bsum[2], acc[i][3] + bsum[3]);
        float4 o1 = make_float4(acc[i][4] + bsum[4], acc[i][5] + bsum[5],
                                acc[i][6] + bsum[6], acc[i][7] + bsum[7]);
        float* crow = C + (size_t)row * N + col0 + tx * 8;
        *(float4*)(crow)     = o0;
        *(float4*)(crow + 4) = o1;
    }
}

// ---------------------------------------------------------------------------
// Recurrent LSTM layer. Sync protocol per step t (NO atomics, NO exotic ops):
//   wait+load: thread tid<128 acquire-polls flag[tid] until >= t, then
//              immediately ld.cg's producer-CTA-tid's 32B of h_{t-1} into
//              smem (acquire in the same thread orders the data load; .cg
//              skips the non-coherent L1). One __syncthreads after.
//   work:      scalar FFMA matvec (reg-resident W_hh) + butterfly reduce +
//              cell update (fast-exp activations).
//   publish:   lane0 -> smem; sync; tid0 st.cg's CTA's 8 h values, then
//              st.release flag[bid] = t+1 (single-thread release ordering).
// Flags monotonic (1 private 128B line per CTA) -> no reset, no ABA.
// Double buffer safe: flag >= t implies producer consumed h_{t-2}, so
// buf[t&1] is reusable.
// ---------------------------------------------------------------------------
__global__ __launch_bounds__(256, 1)
void lstm_layer_kernel(const float* __restrict__ Whh,   // [4H][H]
                       const float* __restrict__ G,     // [T][4H]
                       float* __restrict__ seq,         // [T][H]
                       float* __restrict__ hT, float* __restrict__ cT,
                       float* __restrict__ hbuf,        // [2][H]
                       unsigned* __restrict__ flag)     // [NCTA*FPAD], zeroed
{
    const int tid  = threadIdx.x;
    const int warp = tid >> 5;
    const int lane = tid & 31;
    const int unit = blockIdx.x * UPB + warp;

    // Register-resident weights: lane covers h indices i*128 + lane*4 + c
    float4 w[4][8];
    #pragma unroll
    for (int g = 0; g < 4; g++) {
        const float4* wr = (const float4*)(Whh + (size_t)(g * Hn + unit) * Hn);
        #pragma unroll
        for (int i = 0; i < 8; i++)
            w[g][i] = wr[i * 32 + lane];
    }

    __shared__ float4 sh[Hn / 4];    // staged h_{t-1}
    __shared__ float  sh_h[UPB];     // this CTA's 8 fresh h values

    float c = 0.f;
    float4* mybuf0 = (float4*)(hbuf) + blockIdx.x * 2;       // slot 0, this CTA's 32B
    float4* mybuf1 = (float4*)(hbuf + Hn) + blockIdx.x * 2;  // slot 1

    #pragma unroll 1
    for (int t = 0; t < Tn; t++) {
        // prefetch gate preactivations (independent of h -> overlaps the wait)
        const float* gp = G + (size_t)t * FH + unit;
        float gv0 = __ldg(gp);
        float gv1 = __ldg(gp + Hn);
        float gv2 = __ldg(gp + 2 * Hn);
        float gv3 = __ldg(gp + 3 * Hn);

        float a0 = 0.f, a1 = 0.f, a2 = 0.f, a3 = 0.f;
        if (t > 0) {
            // fused distributed wait + data fetch: 1 thread per producer CTA
            if (tid < NCTA) {
                const unsigned* fp = flag + (tid << 5);
                while (ld_acq_u32(fp) < (unsigned)t) { }
                const float4* src = (const float4*)(hbuf + ((t - 1) & 1) * Hn)
                                    + tid * 2;
                sh[tid * 2]     = ld_cg_v4(src);
                sh[tid * 2 + 1] = ld_cg_v4(src + 1);
            }
            __syncthreads();

            // scalar FFMA matvec: 128 FFMA/lane over 4 gates
            #pragma unroll
            for (int i = 0; i < 8; i++) {
                float4 h4 = sh[i * 32 + lane];
                a0 += w[0][i].x * h4.x; a0 += w[0][i].y * h4.y; a0 += w[0][i].z * h4.z; a0 += w[0][i].w * h4.w;
                a1 += w[1][i].x * h4.x; a1 += w[1][i].y * h4.y; a1 += w[1][i].z * h4.z; a1 += w[1][i].w * h4.w;
                a2 += w[2][i].x * h4.x; a2 += w[2][i].y * h4.y; a2 += w[2][i].z * h4.z; a2 += w[2][i].w * h4.w;
                a3 += w[3][i].x * h4.x; a3 += w[3][i].y * h4.y; a3 += w[3][i].z * h4.z; a3 += w[3][i].w * h4.w;
            }
        }

        // full-warp butterfly reduce (all lanes end with totals)
        #pragma unroll
        for (int off = 16; off; off >>= 1) {
            a0 += __shfl_xor_sync(0xFFFFFFFFu, a0, off);
            a1 += __shfl_xor_sync(0xFFFFFFFFu, a1, off);
            a2 += __shfl_xor_sync(0xFFFFFFFFu, a2, off);
            a3 += __shfl_xor_sync(0xFFFFFFFFu, a3, off);
        }

        float ig = sig_f(gv0 + a0);
        float fg = sig_f(gv1 + a1);
        float gg = tanh_f(gv2 + a2);
        float og = sig_f(gv3 + a3);
        c = fg * c + ig * gg;
        float h = og * tanh_f(c);

        if (lane == 0) {
            sh_h[warp] = h;
            seq[(size_t)t * Hn + unit] = h;
            if (t == Tn - 1) { hT[unit] = h; cT[unit] = c; }
        }
        __syncthreads();

        if (tid == 0) {
            // publish this CTA's 8 h values (two 16B stores) then release flag
            float4* dst = (t & 1) ? mybuf1 : mybuf0;
            st_cg_v4(dst,     make_float4(sh_h[0], sh_h[1], sh_h[2], sh_h[3]));
            st_cg_v4(dst + 1, make_float4(sh_h[4], sh_h[5], sh_h[6], sh_h[7]));
            st_rel_u32(flag + (blockIdx.x << 5), (unsigned)(t + 1));
        }
    }
}

// ---------------------------------------------------------------------------
// Launch: memset flags -> GEMM0 -> layer0 -> GEMM1 -> layer1
// ---------------------------------------------------------------------------
extern "C" void kernel_launch(void* const* d_in, const int* in_sizes, int n_in,
                              void* d_out, int out_size)
{
    const int*   tok = (const int*)d_in[0];
    const float* emb = (const float*)d_in[1];
    const float* Wih = (const float*)d_in[2];
    const float* Whh = (const float*)d_in[3];
    const float* bih = (const float*)d_in[4];
    const float* bhh = (const float*)d_in[5];
    float* out = (float*)d_out;

    float *G, *h0seq, *hbuf;
    unsigned* flag;
    cudaGetSymbolAddress((void**)&G,     d_G);
    cudaGetSymbolAddress((void**)&h0seq, d_h0seq);
    cudaGetSymbolAddress((void**)&hbuf,  d_hbuf);
    cudaGetSymbolAddress((void**)&flag,  d_flag);

    // zero both layers' flags (deterministic across graph replays)
    cudaMemsetAsync(flag, 0, sizeof(unsigned) * 2 * NCTA * FPAD, 0);

    float* outs = out;                        // [T][H]
    float* hTp  = out + (size_t)Tn * Hn;      // [L][H]
    float* cTp  = hTp + 2 * Hn;               // [L][H]

    const int gemm_grid = (Tn / BM) * (FH / BN);   // 1024

    // Layer 0 input projection: G = emb[tok] @ W_ih0^T + b_ih0 + b_hh0
    gemm_nt_bias<<<gemm_grid, 256>>>(emb, tok, Wih, bih, bhh, G, FH, Hn);

    // Layer 0 recurrence
    lstm_layer_kernel<<<NCTA, 256>>>(Whh, G, h0seq, hTp, cTp,
                                     hbuf, flag);

    // Layer 1 input projection: G = h0seq @ W_ih1^T + b_ih1 + b_hh1
    gemm_nt_bias<<<gemm_grid, 256>>>(h0seq, nullptr, Wih + (size_t)FH * Hn,
                                     bih + FH, bhh + FH, G, FH, Hn);

    // Layer 1 recurrence (writes outs + final states)
    lstm_layer_kernel<<<NCTA, 256>>>(Whh + (size_t)FH * Hn, G, outs,
                                     hTp + Hn, cTp + Hn,
                                     hbuf + 2 * Hn, flag + NCTA * FPAD);
}